// round 17
// baseline (speedup 1.0000x reference)
#include <cuda_runtime.h>

#define B_  128
#define N_  4096
#define K_  100
#define P_  4096
#define T_  1024          // threads per block
#define NB_ 512           // LUT buckets
#define NBLK_ (2 * B_)    // two blocks per row

// Device global (no allocation in kernel_launch, per harness rules).
// g_pub[i] = {packed(s,s2) as double, flag}; flags reset by block 0 each run.
__device__ double2 g_pub[NBLK_];

#define F_INF __int_as_float(0x7f800000)

// ---------------------------------------------------------------------------
// 256 blocks, 2 per row (block 2r+h: row r, half h). 1024 threads each.
// 2 blocks co-resident per SM (regs capped at 32 via launch_bounds) =>
// all 256 blocks in wave 1 => poll-based completion is deadlock-free, and
// the two blocks of an SM interleave their latency-bound phase chains.
//   Front (redundant per half): t/a float4 load FIRST -> sign-only scan ->
//     bar1 -> warps 0-3 derive shift, 100 threads gather -> bar2 ->
//     rank-sort (8 thr/elem) -> bar3 -> 512-entry lower_bound LUT -> bar3b
//   Phase 4+5 (split): 2 points/thread over this half's 2048 points;
//     LUT -> verify walk -> 2 float2 candidates; exact jnp.argmin
//     first-index tie-break (orig index read only on exact distance tie);
//     f32 accumulate, f64 warp combine -> partial {s, s2}
//   Publish: pack s,s2 (f32 each) into one double; {packed, flag} in ONE
//     st.global.v2.f64. Block 0's warp 0 polls all 256 entries (8/lane),
//     combines halves per row, loss_r = s2/M - (s/M)^2, means, writes out.
// ---------------------------------------------------------------------------
__global__ void __launch_bounds__(T_, 2)
k_fused(const float* __restrict__ preds,
        const float* __restrict__ target,
        const float* __restrict__ Xffp,
        const float* __restrict__ amp,
        const float* __restrict__ pointx,
        float* __restrict__ out)
{
    const int blk  = blockIdx.x;          // 0..255
    const int row  = blk >> 1;
    const int half = blk & 1;
    const int tid = threadIdx.x;          // 1024
    const int w   = tid >> 5, l = tid & 31;

    const float* t = target + (size_t)row * N_;
    const float* a = amp    + (size_t)row * N_;
    const float* p = preds  + (size_t)row * N_;
    const float* x = Xffp   + (size_t)row * N_;

    // ---- Critical loads FIRST: t/a gate the whole phase chain ----
    const float4 tv4 = ((const float4*)t)[tid];
    const float4 av4 = ((const float4*)a)[tid];

    // this half's pointx (needed only in Phase 4)
    float px[2];
    #pragma unroll
    for (int j = 0; j < 2; j++) px[j] = pointx[half * 2048 + tid + j * T_];

    // Full-row L1 prefetch of x/p, issued last so it can't delay t/a.
    if (tid < 128)
        asm volatile("prefetch.global.L1 [%0];" :: "l"(x + tid * 32));
    else if (tid < 256)
        asm volatile("prefetch.global.L1 [%0];" :: "l"(p + (tid - 128) * 32));

    // ---- Phase 1: min index with u>=0, max index with u<=0 (sign-only) ----
    int minGe = N_;
    int maxLe = -1;
    {
        const float tv[4] = {tv4.x, tv4.y, tv4.z, tv4.w};
        const float av[4] = {av4.x, av4.y, av4.z, av4.w};
        #pragma unroll
        for (int c = 3; c >= 0; c--) {       // descending: first match = min idx
            int  sgn = __float_as_int(tv[c]) ^ __float_as_int(av[c]);
            bool zer = (tv[c] == 0.0f);
            if (zer || sgn >= 0) minGe = tid * 4 + c;       // u >= 0
        }
        #pragma unroll
        for (int c = 0; c <= 3; c++) {       // ascending: last match = max idx
            int  sgn = __float_as_int(tv[c]) ^ __float_as_int(av[c]);
            bool zer = (tv[c] == 0.0f);
            if (zer || sgn < 0) maxLe = tid * 4 + c;        // u <= 0
        }
    }
    minGe = __reduce_min_sync(0xffffffffu, minGe);
    maxLe = __reduce_max_sync(0xffffffffu, maxLe);
    __shared__ int   sMin[32], sMax[32];
    __shared__ float sFL[4];                 // t0, a0, tN, aN from registers
    if (l == 0) { sMin[w] = minGe; sMax[w] = maxLe; }
    if (tid == 0)      { sFL[0] = tv4.x; sFL[1] = av4.x; }
    if (tid == T_ - 1) { sFL[2] = tv4.w; sFL[3] = av4.w; }   // t[4095], a[4095]
    __syncthreads();                                         // barrier 1

    // ---- Phase 2: warps 0-3 each derive shift, 100 threads gather ----
    __shared__ float sX[K_], sD[K_];
    if (tid < 128) {                          // full warps 0-3 only
        int mg = __reduce_min_sync(0xffffffffu, sMin[l]);    // same in all 4 warps
        int ml = __reduce_max_sync(0xffffffffu, sMax[l]);
        int j_left  = (mg == N_) ? 0 : mg;                   // jnp.argmax all-False -> 0
        int m_right = (ml < 0)   ? 0 : (N_ - 1 - ml);
        // u < 0  <=>  sign(t)^sign(a) set and t != 0 (division-free)
        bool firstNeg = ((__float_as_int(sFL[0]) ^ __float_as_int(sFL[1])) < 0)
                        && (sFL[0] != 0.0f);
        bool lastNeg  = ((__float_as_int(sFL[2]) ^ __float_as_int(sFL[3])) < 0)
                        && (sFL[2] != 0.0f);
        const int shift = (lastNeg && firstNeg) ? -(j_left + 1) : m_right;
        if (tid < K_) {
            int src = (tid - shift) % N_;
            if (src < 0) src += N_;
            sX[tid] = x[src];                                 // prefetched, L1-hot
            sD[tid] = (t[src] - p[src]) / a[src];             // == t/a - p/a to ~1ulp
        }
    }
    __syncthreads();                                         // barrier 2

    // ---- Phase 3: stable rank-sort, 8 threads per element ----
    __shared__ float  sXs[K_];                 // sorted keys (search)
    __shared__ float2 sXD[K_];                 // {x, d} pairs (candidates)
    __shared__ int    sIdx[K_];                // orig index (tie-break only)
    {
        const int k = tid >> 3, part = tid & 7;
        if (k < K_) {
            float v = sX[k];
            int r = 0;
            for (int j = part; j < K_; j += 8) {
                float u = sX[j];
                r += (u < v) || (u == v && j < k);
            }
            r += __shfl_down_sync(0xffffffffu, r, 4, 8);
            r += __shfl_down_sync(0xffffffffu, r, 2, 8);
            r += __shfl_down_sync(0xffffffffu, r, 1, 8);
            if (part == 0) {
                sXs[r]  = v;
                sXD[r]  = make_float2(v, sD[k]);
                sIdx[r] = k;
            }
        }
    }
    __syncthreads();                                         // barrier 3

    // ---- Phase 3b: lower_bound LUT over NB_ uniform buckets ----
    __shared__ int   sLUT[NB_];
    __shared__ float sRange[2];               // xmin, inv
    if (tid < NB_) {
        float xmin = sXs[0];
        float xmax = sXs[K_ - 1];
        float wB   = (xmax - xmin) * (1.0f / NB_);
        float edge = fmaf((float)tid, wB, xmin);
        int p0 = 0;
        #pragma unroll
        for (int step = 64; step >= 1; step >>= 1)
            if (p0 + step <= K_ && sXs[p0 + step - 1] < edge) p0 += step;
        sLUT[tid] = p0;                        // #values < edge
        if (tid == 0) {
            float range = xmax - xmin;
            sRange[0] = xmin;
            sRange[1] = (range > 0.f) ? ((float)NB_ / range) : 0.f;
        }
    }
    __syncthreads();                                         // barrier 3b

    // ---- Phase 4+5: LUT-guided NN + partial sums, 2 points/thread ----
    const float xmin = sRange[0];
    const float inv  = sRange[1];

    float s = 0.f, s2 = 0.f;
    #pragma unroll
    for (int j = 0; j < 2; j++) {
        const int   pi = half * 2048 + tid + j * T_;
        const float pv = px[j];
        int g = (int)((pv - xmin) * inv);
        g = min(max(g, 0), NB_ - 1);
        int pos = sLUT[g];
        // verify walk -> exact lower_bound (robust to bucket-edge rounding)
        while (pos < K_ && sXs[pos] < pv) ++pos;
        while (pos > 0 && sXs[pos - 1] >= pv) --pos;
        // two candidates: pos-1 (strictly < pv) and pos (>= pv)
        float dL = F_INF, vL = 0.f;
        if (pos > 0) {
            float2 c = sXD[pos - 1];
            dL = fabsf(pv - c.x); vL = c.y;
        }
        float dR = F_INF, vR = 0.f;
        if (pos < K_) {
            float2 c = sXD[pos];
            dR = fabsf(pv - c.x); vR = c.y;
        }
        bool takeL;
        if (dL != dR) {
            takeL = (dL < dR);
        } else {
            // exact tie (rare): jnp.argmin keeps the smaller ORIGINAL index
            int iL = (pos > 0)  ? sIdx[pos - 1] : 0x7fffffff;
            int iR = (pos < K_) ? sIdx[pos]     : 0x7fffffff;
            takeL = (iL < iR);
        }
        float dv = takeL ? vL : vR;
        if (pi >= 1) {                         // diff[:, 1:] excludes point 0
            s  += dv;
            s2  = fmaf(dv, dv, s2);
        }
    }
    #pragma unroll
    for (int o = 16; o > 0; o >>= 1) {
        s  += __shfl_down_sync(0xffffffffu, s,  o);
        s2 += __shfl_down_sync(0xffffffffu, s2, o);
    }
    __shared__ float rs[32], rs2[32];
    if (l == 0) { rs[w] = s; rs2[w] = s2; }
    __syncthreads();                                         // barrier 4 (last)

    if (w != 0) return;                       // warps 1-31 are done

    // ---- warp 0: combine partials, publish packed {s,s2} + flag ----
    double ds  = (double)rs [l];
    double ds2 = (double)rs2[l];
    #pragma unroll
    for (int o = 16; o > 0; o >>= 1) {
        ds  += __shfl_down_sync(0xffffffffu, ds,  o);
        ds2 += __shfl_down_sync(0xffffffffu, ds2, o);
    }
    if (l == 0) {
        // pack the two f32 partial sums into one double (bitwise)
        double packed = __hiloint2double(__float_as_int((float)ds2),
                                         __float_as_int((float)ds));
        asm volatile("st.global.v2.f64 [%0], {%1, %2};"
                     :: "l"(&g_pub[blk]), "d"(packed), "d"(1.0) : "memory");
    }
    if (blk != 0) return;

    // Block 0, warp 0: poll all 256 entries (rows l, l+32, l+64, l+96;
    // each row has entries 2r and 2r+1).
    double pk[8];
    bool done;
    do {
        done = true;
        #pragma unroll
        for (int q = 0; q < 4; q++) {
            int r = l + q * 32;
            double f0, f1;
            asm volatile("ld.volatile.global.v2.f64 {%0,%1}, [%2];"
                         : "=d"(pk[2*q]),   "=d"(f0) : "l"(&g_pub[2*r    ]));
            asm volatile("ld.volatile.global.v2.f64 {%0,%1}, [%2];"
                         : "=d"(pk[2*q+1]), "=d"(f1) : "l"(&g_pub[2*r + 1]));
            done = done && (f0 != 0.0) && (f1 != 0.0);
        }
    } while (!__all_sync(0xffffffffu, done));

    double sum = 0.0;
    const double M = (double)(P_ - 1);        // 4095, ddof=0
    #pragma unroll
    for (int q = 0; q < 4; q++) {
        double se  = (double)__int_as_float(__double2loint(pk[2*q]));
        double se2 = (double)__int_as_float(__double2hiint(pk[2*q]));
        double so  = (double)__int_as_float(__double2loint(pk[2*q+1]));
        double so2 = (double)__int_as_float(__double2hiint(pk[2*q+1]));
        double sr  = se + so;
        double sr2 = se2 + so2;
        double mean = sr / M;
        sum += sr2 / M - mean * mean;          // loss of this row
    }
    #pragma unroll
    for (int o = 16; o > 0; o >>= 1)
        sum += __shfl_down_sync(0xffffffffu, sum, o);
    if (l == 0)
        out[0] = (float)(sum / (double)B_);

    // Reset flags for the next graph replay (stream order protects replays).
    #pragma unroll
    for (int q = 0; q < 4; q++) {
        int r = l + q * 32;
        g_pub[2*r    ].y = 0.0;
        g_pub[2*r + 1].y = 0.0;
    }
}

// ---------------------------------------------------------------------------
// Inputs (metadata order): preds, target, Xffp, dXffp_Amp, pointx
// Output: scalar float32
// ---------------------------------------------------------------------------
extern "C" void kernel_launch(void* const* d_in, const int* in_sizes, int n_in,
                              void* d_out, int out_size)
{
    const float* preds  = (const float*)d_in[0];
    const float* target = (const float*)d_in[1];
    const float* Xffp   = (const float*)d_in[2];
    const float* amp    = (const float*)d_in[3];
    const float* pointx = (const float*)d_in[4];

    k_fused<<<NBLK_, T_>>>(preds, target, Xffp, amp, pointx, (float*)d_out);
}